// round 8
// baseline (speedup 1.0000x reference)
#include <cuda_runtime.h>
#include <cuda_bf16.h>
#include <cstdint>

#define N_NODES 50000
#define N_EDGES 640000
#define HID 128
#define KSTR 136                     // padded k-stride (bf16 elems)
#define KSTRB (KSTR * 2)             // 272 bytes
#define TILE_B (128 * KSTRB)         // 34816 bytes per bf16 tile
#define NBLK 196                     // ceil(N_NODES/256)

// ---------------- scratch (static __device__; no allocations) --------------
__device__ float4 g_proj4[16 * (HID / 4)];
__device__ int    g_idx64;
__device__ int    g_cnt[N_NODES];
__device__ int    g_off[N_NODES + 1];
__device__ int    g_cur[N_NODES];
__device__ int    g_bsum[256];
__device__ int    g_bpre[256];
__device__ int      g_dst[N_EDGES];
__device__ unsigned g_srch[N_EDGES];     // (src << 4) | h
__device__ unsigned g_packed[N_EDGES];   // dst-sorted (src << 4) | h
// bf16 hi/lo weight tiles, transposed [n][k], stride KSTR
__device__ __align__(16) unsigned short g_w1h[128 * KSTR];
__device__ __align__(16) unsigned short g_w1l[128 * KSTR];
__device__ __align__(16) unsigned short g_w2h[128 * KSTR];
__device__ __align__(16) unsigned short g_w2l[128 * KSTR];

// ---------------- helpers ---------------------------------------------------
__device__ __forceinline__ uint32_t smem_u32(const void* p) {
    uint32_t a;
    asm("{ .reg .u64 t; cvta.to.shared.u64 t, %1; cvt.u32.u64 %0, t; }"
        : "=r"(a) : "l"(p));
    return a;
}
__device__ __forceinline__ void ldsm4(uint32_t* r, uint32_t a) {
    asm volatile("ldmatrix.sync.aligned.m8n8.x4.shared.b16 {%0,%1,%2,%3}, [%4];"
                 : "=r"(r[0]), "=r"(r[1]), "=r"(r[2]), "=r"(r[3]) : "r"(a));
}
__device__ __forceinline__ void mma_bf16(float* d, const uint32_t* a,
                                         uint32_t b0, uint32_t b1) {
    asm volatile(
        "mma.sync.aligned.m16n8k16.row.col.f32.bf16.bf16.f32 "
        "{%0,%1,%2,%3}, {%4,%5,%6,%7}, {%8,%9}, {%0,%1,%2,%3};"
        : "+f"(d[0]), "+f"(d[1]), "+f"(d[2]), "+f"(d[3])
        : "r"(a[0]), "r"(a[1]), "r"(a[2]), "r"(a[3]), "r"(b0), "r"(b1));
}
__device__ __forceinline__ uint32_t splitpair(float v0, float v1, uint32_t& lo) {
    __nv_bfloat16 h0 = __float2bfloat16(v0), h1 = __float2bfloat16(v1);
    __nv_bfloat16 l0 = __float2bfloat16(v0 - __bfloat162float(h0));
    __nv_bfloat16 l1 = __float2bfloat16(v1 - __bfloat162float(h1));
    lo = (uint32_t)__bfloat16_as_ushort(l0) |
         ((uint32_t)__bfloat16_as_ushort(l1) << 16);
    return (uint32_t)__bfloat16_as_ushort(h0) |
           ((uint32_t)__bfloat16_as_ushort(h1) << 16);
}

// ---------------------------------------------------------------------------
// setup: blocks 0..195 zero counts (+ block0 dtype probe),
//        blocks 196..203 proj table, blocks 204..339 weight split
// ---------------------------------------------------------------------------
__global__ void setup_kernel(const unsigned* __restrict__ ei_raw,
                             const float* __restrict__ emb,
                             const float* __restrict__ We,
                             const float* __restrict__ be,
                             const float* __restrict__ W1,
                             const float* __restrict__ W2) {
    int b = blockIdx.x;
    if (b < NBLK) {
        int i = b * 256 + threadIdx.x;
        if (i < N_NODES) g_cnt[i] = 0;
        if (b == 0 && threadIdx.x == 0) {
            unsigned acc = 0;
#pragma unroll
            for (int k = 0; k < 128; k++) acc |= ei_raw[2 * k + 1];
            g_idx64 = (acc == 0u) ? 1 : 0;
        }
    } else if (b < NBLK + 8) {
        int tid = (b - NBLK) * 256 + threadIdx.x;
        if (tid < 16 * HID) {
            int t = tid >> 7, j = tid & 127;
            float s = be[j];
#pragma unroll
            for (int d = 0; d < 8; d++)
                s = fmaf(emb[t * 8 + d], We[d * HID + j], s);
            ((float*)g_proj4)[tid] = s;
        }
    } else {
        int tid = (b - NBLK - 8) * 256 + threadIdx.x;
        if (tid < 2 * 128 * KSTR) {
            int mat = tid / (128 * KSTR);
            int rem = tid % (128 * KSTR);
            int n = rem / KSTR;
            int k = rem % KSTR;
            unsigned short hv = 0, lv = 0;
            if (k < 128) {
                const float* W = mat ? W2 : W1;
                float w = W[k * HID + n];
                __nv_bfloat16 h = __float2bfloat16(w);
                __nv_bfloat16 l = __float2bfloat16(w - __bfloat162float(h));
                hv = __bfloat16_as_ushort(h);
                lv = __bfloat16_as_ushort(l);
            }
            (mat ? g_w2h : g_w1h)[n * KSTR + k] = hv;
            (mat ? g_w2l : g_w1l)[n * KSTR + k] = lv;
        }
    }
}

// ---------------------------------------------------------------------------
// conv + hist: 4 edges per thread for ILP
// ---------------------------------------------------------------------------
__global__ void conv_kernel(const void* __restrict__ ei_v,
                            const void* __restrict__ ea_v) {
    int e0 = (blockIdx.x * blockDim.x + threadIdx.x) * 4;
    if (e0 >= N_EDGES) return;
    if (g_idx64) {
        const long long* ei = (const long long*)ei_v;
        const long long* ea = (const long long*)ea_v;
#pragma unroll
        for (int j = 0; j < 4; j++) {
            int e = e0 + j;
            int src = (int)ei[e], dst = (int)ei[N_EDGES + e];
            int h = (int)((ea[3LL * e] + 3 * ea[3LL * e + 1] + 7 * ea[3LL * e + 2]) & 15);
            g_srch[e] = ((unsigned)src << 4) | (unsigned)h;
            g_dst[e] = dst;
            atomicAdd(&g_cnt[dst], 1);
        }
    } else {
        const int* ei = (const int*)ei_v;
        const int* ea = (const int*)ea_v;
#pragma unroll
        for (int j = 0; j < 4; j++) {
            int e = e0 + j;
            int src = ei[e], dst = ei[N_EDGES + e];
            int h = (ea[3 * e] + 3 * ea[3 * e + 1] + 7 * ea[3 * e + 2]) & 15;
            g_srch[e] = ((unsigned)src << 4) | (unsigned)h;
            g_dst[e] = dst;
            atomicAdd(&g_cnt[dst], 1);
        }
    }
}

// ---------------------------------------------------------------------------
// hierarchical exclusive scan of g_cnt -> g_off/g_cur
// ---------------------------------------------------------------------------
__global__ void scan1_kernel() {
    __shared__ int s[256];
    int tid = threadIdx.x;
    int i = blockIdx.x * 256 + tid;
    int c = (i < N_NODES) ? g_cnt[i] : 0;
    s[tid] = c;
    __syncthreads();
#pragma unroll
    for (int d = 1; d < 256; d <<= 1) {
        int t = (tid >= d) ? s[tid - d] : 0;
        __syncthreads();
        s[tid] += t;
        __syncthreads();
    }
    if (i < N_NODES) g_off[i] = s[tid] - c;
    if (tid == 255) g_bsum[blockIdx.x] = s[255];
}

__global__ void scan2_kernel() {
    __shared__ int s[256];
    int tid = threadIdx.x;
    int v = (tid < NBLK) ? g_bsum[tid] : 0;
    s[tid] = v;
    __syncthreads();
#pragma unroll
    for (int d = 1; d < 256; d <<= 1) {
        int t = (tid >= d) ? s[tid - d] : 0;
        __syncthreads();
        s[tid] += t;
        __syncthreads();
    }
    g_bpre[tid] = s[tid] - v;
}

__global__ void scan3_kernel() {
    int tid = threadIdx.x;
    int i = blockIdx.x * 256 + tid;
    if (i < N_NODES) {
        int o = g_off[i] + g_bpre[blockIdx.x];
        g_off[i] = o;
        g_cur[i] = o;
    }
    if (i == 0) g_off[N_NODES] = N_EDGES;
}

__global__ void scatter_kernel() {
    int e = blockIdx.x * blockDim.x + threadIdx.x;
    if (e >= N_EDGES) return;
    int pos = atomicAdd(&g_cur[g_dst[e]], 1);
    g_packed[pos] = g_srch[e];
}

// ---------------------------------------------------------------------------
// fused MLP: per-CTA aggregation (warp-per-node, 4-deep gather pipeline)
// straight into the bf16 hi/lo z smem tile, then mma.sync bf16x3 GEMMs.
// ---------------------------------------------------------------------------
#define SM_B1  0
#define SM_B2  512
#define SM_ZH  1024
#define SM_ZL  (SM_ZH + TILE_B)
#define SM_W1H (SM_ZL + TILE_B)
#define SM_W1L (SM_W1H + TILE_B)
#define SM_W2H (SM_W1L + TILE_B)
#define SM_W2L (SM_W2H + TILE_B)
#define SM_TOT (SM_W2L + TILE_B)     // 209920 bytes

__device__ __forceinline__ void gemm128(uint32_t sb, uint32_t zh, uint32_t zl,
                                        uint32_t wh, uint32_t wl,
                                        uint32_t aByte, uint32_t bByte,
                                        float acc[16][4]) {
#pragma unroll
    for (int ks = 0; ks < 8; ks++) {
        uint32_t k0b = ks * 32;
        uint32_t ah[4], al[4];
        ldsm4(ah, sb + zh + aByte + k0b);
        ldsm4(al, sb + zl + aByte + k0b);
#pragma unroll
        for (int np = 0; np < 8; np++) {
            uint32_t wo = bByte + np * (16 * KSTRB) + k0b;
            uint32_t wH[4], wL[4];
            ldsm4(wH, sb + wh + wo);
            ldsm4(wL, sb + wl + wo);
            mma_bf16(acc[2 * np],     ah, wH[0], wH[1]);
            mma_bf16(acc[2 * np],     ah, wL[0], wL[1]);
            mma_bf16(acc[2 * np],     al, wH[0], wH[1]);
            mma_bf16(acc[2 * np + 1], ah, wH[2], wH[3]);
            mma_bf16(acc[2 * np + 1], ah, wL[2], wL[3]);
            mma_bf16(acc[2 * np + 1], al, wH[2], wH[3]);
        }
    }
}

__global__ void __launch_bounds__(256, 1)
mlp_fused_kernel(const float4* __restrict__ x4,
                 const float* __restrict__ epsp,
                 const float* __restrict__ b1, const float* __restrict__ b2,
                 float* __restrict__ out) {
    extern __shared__ char smem[];
    const uint32_t sb = smem_u32(smem);
    const int tid = threadIdx.x, wid = tid >> 5, lane = tid & 31;
    const int base = blockIdx.x * 128;

    if (tid < 128) {
        ((float*)(smem + SM_B1))[tid] = b1[tid];
        ((float*)(smem + SM_B2))[tid] = b2[tid];
    }
    // weight tiles: straight copies
    {
        const uint4* s[4] = {(const uint4*)g_w1h, (const uint4*)g_w1l,
                             (const uint4*)g_w2h, (const uint4*)g_w2l};
        uint4* d[4] = {(uint4*)(smem + SM_W1H), (uint4*)(smem + SM_W1L),
                       (uint4*)(smem + SM_W2H), (uint4*)(smem + SM_W2L)};
#pragma unroll
        for (int a = 0; a < 4; a++)
            for (int i = tid; i < TILE_B / 16; i += 256) d[a][i] = s[a][i];
    }

    // fused aggregation: warp wid handles 16 nodes, writes z tile directly
    {
        const float e1 = 1.0f + __ldg(epsp);
        for (int t = 0; t < 16; t++) {
            const int row = wid * 16 + t;
            const int node = base + row;
            float4 acc = make_float4(0.f, 0.f, 0.f, 0.f);
            if (node < N_NODES) {
                int beg = g_off[node], end = g_off[node + 1];
                for (int e = beg; e < end; e += 4) {
                    int m = end - e;
                    unsigned pk[4];
#pragma unroll
                    for (int j = 0; j < 4; j++)
                        pk[j] = (j < m) ? __ldg(&g_packed[e + j]) : 0u;
                    float4 xv[4], pv[4];
#pragma unroll
                    for (int j = 0; j < 4; j++) {
                        if (j < m) {
                            xv[j] = __ldg(&x4[(size_t)(pk[j] >> 4) * 32 + lane]);
                            pv[j] = __ldg(&g_proj4[(pk[j] & 15u) * 32 + lane]);
                        }
                    }
#pragma unroll
                    for (int j = 0; j < 4; j++) {
                        if (j < m) {
                            acc.x += fmaxf(xv[j].x + pv[j].x, 0.f);
                            acc.y += fmaxf(xv[j].y + pv[j].y, 0.f);
                            acc.z += fmaxf(xv[j].z + pv[j].z, 0.f);
                            acc.w += fmaxf(xv[j].w + pv[j].w, 0.f);
                        }
                    }
                }
                float4 xn = __ldg(&x4[(size_t)node * 32 + lane]);
                acc.x = fmaf(e1, xn.x, acc.x);
                acc.y = fmaf(e1, xn.y, acc.y);
                acc.z = fmaf(e1, xn.z, acc.z);
                acc.w = fmaf(e1, xn.w, acc.w);
            }
            uint2 hv, lv;
            hv.x = splitpair(acc.x, acc.y, lv.x);
            hv.y = splitpair(acc.z, acc.w, lv.y);
            *(uint2*)(smem + SM_ZH + row * KSTRB + lane * 8) = hv;
            *(uint2*)(smem + SM_ZL + row * KSTRB + lane * 8) = lv;
        }
    }
    __syncthreads();

    const int aRow = wid * 16 + (lane & 7) + ((lane & 8) ? 8 : 0);
    const uint32_t aByte = (uint32_t)aRow * KSTRB + (((lane & 16) ? 8 : 0) * 2);
    const int bN = (lane & 7) + ((lane & 16) ? 8 : 0);
    const uint32_t bByte = (uint32_t)bN * KSTRB + (((lane & 8) ? 8 : 0) * 2);

    const int g4 = lane >> 2, t4 = lane & 3;
    const int rloc = wid * 16 + g4;

    float acc[16][4];
#pragma unroll
    for (int nt = 0; nt < 16; nt++)
#pragma unroll
        for (int i = 0; i < 4; i++) acc[nt][i] = 0.f;

    gemm128(sb, SM_ZH, SM_ZL, SM_W1H, SM_W1L, aByte, bByte, acc);

    {
        const float* b1s = (const float*)(smem + SM_B1);
#pragma unroll
        for (int nt = 0; nt < 16; nt++) {
            int col = nt * 8 + 2 * t4;
            float v0 = fmaxf(acc[nt][0] + b1s[col],     0.f);
            float v1 = fmaxf(acc[nt][1] + b1s[col + 1], 0.f);
            float v2 = fmaxf(acc[nt][2] + b1s[col],     0.f);
            float v3 = fmaxf(acc[nt][3] + b1s[col + 1], 0.f);
            uint32_t l0, l1;
            uint32_t h0 = splitpair(v0, v1, l0);
            uint32_t h1 = splitpair(v2, v3, l1);
            uint32_t o0 = rloc * KSTRB + col * 2;
            uint32_t o1 = (rloc + 8) * KSTRB + col * 2;
            *(uint32_t*)(smem + SM_ZH + o0) = h0;
            *(uint32_t*)(smem + SM_ZL + o0) = l0;
            *(uint32_t*)(smem + SM_ZH + o1) = h1;
            *(uint32_t*)(smem + SM_ZL + o1) = l1;
            acc[nt][0] = acc[nt][1] = acc[nt][2] = acc[nt][3] = 0.f;
        }
    }
    __syncwarp();

    gemm128(sb, SM_ZH, SM_ZL, SM_W2H, SM_W2L, aByte, bByte, acc);

    {
        const float* b2s = (const float*)(smem + SM_B2);
        int gr = base + rloc;
#pragma unroll
        for (int nt = 0; nt < 16; nt++) {
            int col = nt * 8 + 2 * t4;
            if (gr < N_NODES) {
                float2 v = make_float2(acc[nt][0] + b2s[col],
                                       acc[nt][1] + b2s[col + 1]);
                *(float2*)&out[(size_t)gr * HID + col] = v;
            }
            if (gr + 8 < N_NODES) {
                float2 v = make_float2(acc[nt][2] + b2s[col],
                                       acc[nt][3] + b2s[col + 1]);
                *(float2*)&out[(size_t)(gr + 8) * HID + col] = v;
            }
        }
    }
}

// ---------------------------------------------------------------------------
extern "C" void kernel_launch(void* const* d_in, const int* in_sizes, int n_in,
                              void* d_out, int out_size) {
    const float* x   = (const float*)d_in[0];
    const void*  ei  = d_in[1];
    const void*  ea  = d_in[2];
    const float* emb = (const float*)d_in[3];
    const float* We  = (const float*)d_in[4];
    const float* be  = (const float*)d_in[5];
    const float* W1  = (const float*)d_in[6];
    const float* b1  = (const float*)d_in[7];
    const float* W2  = (const float*)d_in[8];
    const float* b2  = (const float*)d_in[9];
    const float* eps = (const float*)d_in[10];
    float*       out = (float*)d_out;

    cudaFuncSetAttribute(mlp_fused_kernel,
                         cudaFuncAttributeMaxDynamicSharedMemorySize, SM_TOT);

    setup_kernel<<<NBLK + 8 + 136, 256>>>((const unsigned*)ei, emb, We, be, W1, W2);
    conv_kernel<<<(N_EDGES / 4 + 255) / 256, 256>>>(ei, ea);
    scan1_kernel<<<NBLK, 256>>>();
    scan2_kernel<<<1, 256>>>();
    scan3_kernel<<<NBLK, 256>>>();
    scatter_kernel<<<(N_EDGES + 255) / 256, 256>>>();
    mlp_fused_kernel<<<(N_NODES + 127) / 128, 256, SM_TOT>>>(
        (const float4*)x, eps, b1, b2, out);
}

// round 9
// speedup vs baseline: 1.4694x; 1.4694x over previous
#include <cuda_runtime.h>
#include <cuda_bf16.h>
#include <cstdint>

#define N_NODES 50000
#define N_EDGES 640000
#define HID 128
#define KSTR 136                     // padded k-stride (bf16 elems)
#define KSTRB (KSTR * 2)             // 272 bytes
#define TILE_B (128 * KSTRB)         // 34816 bytes per bf16 tile
#define NBLK 196                     // ceil(N_NODES/256)

// ---------------- scratch (static __device__; no allocations) --------------
__device__ float4 g_aggr4[(size_t)N_NODES * (HID / 4)];
__device__ float4 g_proj4[16 * (HID / 4)];
__device__ int    g_idx64;
__device__ int    g_cnt[N_NODES];
__device__ int    g_off[N_NODES + 1];
__device__ int    g_cur[N_NODES];
__device__ int    g_bsum[256];
__device__ int    g_bpre[256];
__device__ int      g_dst[N_EDGES];
__device__ unsigned g_srch[N_EDGES];     // (src << 4) | h
__device__ unsigned g_packed[N_EDGES];   // dst-sorted (src << 4) | h
// bf16 hi/lo weight tiles, transposed [n][k], stride KSTR
__device__ __align__(16) unsigned short g_w1h[128 * KSTR];
__device__ __align__(16) unsigned short g_w1l[128 * KSTR];
__device__ __align__(16) unsigned short g_w2h[128 * KSTR];
__device__ __align__(16) unsigned short g_w2l[128 * KSTR];

// ---------------- helpers ---------------------------------------------------
__device__ __forceinline__ uint32_t smem_u32(const void* p) {
    uint32_t a;
    asm("{ .reg .u64 t; cvta.to.shared.u64 t, %1; cvt.u32.u64 %0, t; }"
        : "=r"(a) : "l"(p));
    return a;
}
__device__ __forceinline__ void ldsm4(uint32_t* r, uint32_t a) {
    asm volatile("ldmatrix.sync.aligned.m8n8.x4.shared.b16 {%0,%1,%2,%3}, [%4];"
                 : "=r"(r[0]), "=r"(r[1]), "=r"(r[2]), "=r"(r[3]) : "r"(a));
}
__device__ __forceinline__ void mma_bf16(float* d, const uint32_t* a,
                                         uint32_t b0, uint32_t b1) {
    asm volatile(
        "mma.sync.aligned.m16n8k16.row.col.f32.bf16.bf16.f32 "
        "{%0,%1,%2,%3}, {%4,%5,%6,%7}, {%8,%9}, {%0,%1,%2,%3};"
        : "+f"(d[0]), "+f"(d[1]), "+f"(d[2]), "+f"(d[3])
        : "r"(a[0]), "r"(a[1]), "r"(a[2]), "r"(a[3]), "r"(b0), "r"(b1));
}
__device__ __forceinline__ uint32_t splitpair(float v0, float v1, uint32_t& lo) {
    __nv_bfloat16 h0 = __float2bfloat16(v0), h1 = __float2bfloat16(v1);
    __nv_bfloat16 l0 = __float2bfloat16(v0 - __bfloat162float(h0));
    __nv_bfloat16 l1 = __float2bfloat16(v1 - __bfloat162float(h1));
    lo = (uint32_t)__bfloat16_as_ushort(l0) |
         ((uint32_t)__bfloat16_as_ushort(l1) << 16);
    return (uint32_t)__bfloat16_as_ushort(h0) |
           ((uint32_t)__bfloat16_as_ushort(h1) << 16);
}

// ---------------------------------------------------------------------------
// setup: blocks 0..195 zero counts (+ block0 dtype probe),
//        blocks 196..203 proj table, blocks 204..339 weight split
// ---------------------------------------------------------------------------
__global__ void setup_kernel(const unsigned* __restrict__ ei_raw,
                             const float* __restrict__ emb,
                             const float* __restrict__ We,
                             const float* __restrict__ be,
                             const float* __restrict__ W1,
                             const float* __restrict__ W2) {
    int b = blockIdx.x;
    if (b < NBLK) {
        int i = b * 256 + threadIdx.x;
        if (i < N_NODES) g_cnt[i] = 0;
        if (b == 0 && threadIdx.x == 0) {
            unsigned acc = 0;
#pragma unroll
            for (int k = 0; k < 128; k++) acc |= ei_raw[2 * k + 1];
            g_idx64 = (acc == 0u) ? 1 : 0;
        }
    } else if (b < NBLK + 8) {
        int tid = (b - NBLK) * 256 + threadIdx.x;
        if (tid < 16 * HID) {
            int t = tid >> 7, j = tid & 127;
            float s = be[j];
#pragma unroll
            for (int d = 0; d < 8; d++)
                s = fmaf(emb[t * 8 + d], We[d * HID + j], s);
            ((float*)g_proj4)[tid] = s;
        }
    } else {
        int tid = (b - NBLK - 8) * 256 + threadIdx.x;
        if (tid < 2 * 128 * KSTR) {
            int mat = tid / (128 * KSTR);
            int rem = tid % (128 * KSTR);
            int n = rem / KSTR;
            int k = rem % KSTR;
            unsigned short hv = 0, lv = 0;
            if (k < 128) {
                const float* W = mat ? W2 : W1;
                float w = W[k * HID + n];
                __nv_bfloat16 h = __float2bfloat16(w);
                __nv_bfloat16 l = __float2bfloat16(w - __bfloat162float(h));
                hv = __bfloat16_as_ushort(h);
                lv = __bfloat16_as_ushort(l);
            }
            (mat ? g_w2h : g_w1h)[n * KSTR + k] = hv;
            (mat ? g_w2l : g_w1l)[n * KSTR + k] = lv;
        }
    }
}

// ---------------------------------------------------------------------------
// conv + hist: 4 edges per thread for ILP
// ---------------------------------------------------------------------------
__global__ void conv_kernel(const void* __restrict__ ei_v,
                            const void* __restrict__ ea_v) {
    int e0 = (blockIdx.x * blockDim.x + threadIdx.x) * 4;
    if (e0 >= N_EDGES) return;
    if (g_idx64) {
        const long long* ei = (const long long*)ei_v;
        const long long* ea = (const long long*)ea_v;
#pragma unroll
        for (int j = 0; j < 4; j++) {
            int e = e0 + j;
            int src = (int)ei[e], dst = (int)ei[N_EDGES + e];
            int h = (int)((ea[3LL * e] + 3 * ea[3LL * e + 1] + 7 * ea[3LL * e + 2]) & 15);
            g_srch[e] = ((unsigned)src << 4) | (unsigned)h;
            g_dst[e] = dst;
            atomicAdd(&g_cnt[dst], 1);
        }
    } else {
        const int* ei = (const int*)ei_v;
        const int* ea = (const int*)ea_v;
#pragma unroll
        for (int j = 0; j < 4; j++) {
            int e = e0 + j;
            int src = ei[e], dst = ei[N_EDGES + e];
            int h = (ea[3 * e] + 3 * ea[3 * e + 1] + 7 * ea[3 * e + 2]) & 15;
            g_srch[e] = ((unsigned)src << 4) | (unsigned)h;
            g_dst[e] = dst;
            atomicAdd(&g_cnt[dst], 1);
        }
    }
}

// ---------------------------------------------------------------------------
// hierarchical exclusive scan of g_cnt -> g_off/g_cur
// ---------------------------------------------------------------------------
__global__ void scan1_kernel() {
    __shared__ int s[256];
    int tid = threadIdx.x;
    int i = blockIdx.x * 256 + tid;
    int c = (i < N_NODES) ? g_cnt[i] : 0;
    s[tid] = c;
    __syncthreads();
#pragma unroll
    for (int d = 1; d < 256; d <<= 1) {
        int t = (tid >= d) ? s[tid - d] : 0;
        __syncthreads();
        s[tid] += t;
        __syncthreads();
    }
    if (i < N_NODES) g_off[i] = s[tid] - c;
    if (tid == 255) g_bsum[blockIdx.x] = s[255];
}

__global__ void scan2_kernel() {
    __shared__ int s[256];
    int tid = threadIdx.x;
    int v = (tid < NBLK) ? g_bsum[tid] : 0;
    s[tid] = v;
    __syncthreads();
#pragma unroll
    for (int d = 1; d < 256; d <<= 1) {
        int t = (tid >= d) ? s[tid - d] : 0;
        __syncthreads();
        s[tid] += t;
        __syncthreads();
    }
    g_bpre[tid] = s[tid] - v;
}

__global__ void scan3_kernel() {
    int tid = threadIdx.x;
    int i = blockIdx.x * 256 + tid;
    if (i < N_NODES) {
        int o = g_off[i] + g_bpre[blockIdx.x];
        g_off[i] = o;
        g_cur[i] = o;
    }
    if (i == 0) g_off[N_NODES] = N_EDGES;
}

// scatter: 2 edges per thread for ILP
__global__ void scatter_kernel() {
    int e0 = (blockIdx.x * blockDim.x + threadIdx.x) * 2;
    if (e0 >= N_EDGES) return;
#pragma unroll
    for (int j = 0; j < 2; j++) {
        int e = e0 + j;
        int pos = atomicAdd(&g_cur[g_dst[e]], 1);
        g_packed[pos] = g_srch[e];
    }
}

// ---------------------------------------------------------------------------
// aggregate: one warp per node, no atomics, 4-deep gather pipeline.
// aggr[n] = (1+eps)*x[n] + sum_{e in CSR[n]} relu(x[src_e] + proj[h_e])
// ---------------------------------------------------------------------------
__global__ void __launch_bounds__(256)
aggr_kernel(const float4* __restrict__ x4, const float* __restrict__ epsp) {
    int node = (blockIdx.x * blockDim.x + threadIdx.x) >> 5;
    int lane = threadIdx.x & 31;
    if (node >= N_NODES) return;

    int beg = g_off[node], end = g_off[node + 1];
    float4 acc = make_float4(0.f, 0.f, 0.f, 0.f);

    for (int e = beg; e < end; e += 4) {
        int m = end - e;
        unsigned pk[4];
#pragma unroll
        for (int j = 0; j < 4; j++)
            pk[j] = (j < m) ? __ldg(&g_packed[e + j]) : 0u;
        float4 xv[4], pv[4];
#pragma unroll
        for (int j = 0; j < 4; j++) {
            if (j < m) {
                xv[j] = __ldg(&x4[(size_t)(pk[j] >> 4) * 32 + lane]);
                pv[j] = __ldg(&g_proj4[(pk[j] & 15u) * 32 + lane]);
            }
        }
#pragma unroll
        for (int j = 0; j < 4; j++) {
            if (j < m) {
                acc.x += fmaxf(xv[j].x + pv[j].x, 0.f);
                acc.y += fmaxf(xv[j].y + pv[j].y, 0.f);
                acc.z += fmaxf(xv[j].z + pv[j].z, 0.f);
                acc.w += fmaxf(xv[j].w + pv[j].w, 0.f);
            }
        }
    }
    float e1 = 1.0f + __ldg(epsp);
    float4 xn = __ldg(&x4[(size_t)node * 32 + lane]);
    acc.x = fmaf(e1, xn.x, acc.x);
    acc.y = fmaf(e1, xn.y, acc.y);
    acc.z = fmaf(e1, xn.z, acc.z);
    acc.w = fmaf(e1, xn.w, acc.w);
    g_aggr4[(size_t)node * 32 + lane] = acc;
}

// ---------------------------------------------------------------------------
// MLP via mma.sync bf16x3 (proven R5/R7 version)
// ---------------------------------------------------------------------------
#define SM_B1  0
#define SM_B2  512
#define SM_ZH  1024
#define SM_ZL  (SM_ZH + TILE_B)
#define SM_W1H (SM_ZL + TILE_B)
#define SM_W1L (SM_W1H + TILE_B)
#define SM_W2H (SM_W1L + TILE_B)
#define SM_W2L (SM_W2H + TILE_B)
#define SM_TOT (SM_W2L + TILE_B)     // 209920 bytes

__device__ __forceinline__ void gemm128(uint32_t sb, uint32_t zh, uint32_t zl,
                                        uint32_t wh, uint32_t wl,
                                        uint32_t aByte, uint32_t bByte,
                                        float acc[16][4]) {
#pragma unroll
    for (int ks = 0; ks < 8; ks++) {
        uint32_t k0b = ks * 32;
        uint32_t ah[4], al[4];
        ldsm4(ah, sb + zh + aByte + k0b);
        ldsm4(al, sb + zl + aByte + k0b);
#pragma unroll
        for (int np = 0; np < 8; np++) {
            uint32_t wo = bByte + np * (16 * KSTRB) + k0b;
            uint32_t wH[4], wL[4];
            ldsm4(wH, sb + wh + wo);
            ldsm4(wL, sb + wl + wo);
            mma_bf16(acc[2 * np],     ah, wH[0], wH[1]);
            mma_bf16(acc[2 * np],     ah, wL[0], wL[1]);
            mma_bf16(acc[2 * np],     al, wH[0], wH[1]);
            mma_bf16(acc[2 * np + 1], ah, wH[2], wH[3]);
            mma_bf16(acc[2 * np + 1], ah, wL[2], wL[3]);
            mma_bf16(acc[2 * np + 1], al, wH[2], wH[3]);
        }
    }
}

__global__ void __launch_bounds__(256, 1)
mlp_mma_kernel(const float* __restrict__ b1, const float* __restrict__ b2,
               float* __restrict__ out) {
    extern __shared__ char smem[];
    const uint32_t sb = smem_u32(smem);
    const int tid = threadIdx.x, wid = tid >> 5, lane = tid & 31;
    const int base = blockIdx.x * 128;

    if (tid < 128) {
        ((float*)(smem + SM_B1))[tid] = b1[tid];
        ((float*)(smem + SM_B2))[tid] = b2[tid];
    }
    {
        const uint4* s[4] = {(const uint4*)g_w1h, (const uint4*)g_w1l,
                             (const uint4*)g_w2h, (const uint4*)g_w2l};
        uint4* d[4] = {(uint4*)(smem + SM_W1H), (uint4*)(smem + SM_W1L),
                       (uint4*)(smem + SM_W2H), (uint4*)(smem + SM_W2L)};
#pragma unroll
        for (int a = 0; a < 4; a++)
            for (int i = tid; i < TILE_B / 16; i += 256) d[a][i] = s[a][i];
    }

#pragma unroll
    for (int it = 0; it < 16; it++) {
        int idx = tid + it * 256;
        int row = idx >> 5, c4 = idx & 31;
        int g = base + row;
        float4 v = make_float4(0.f, 0.f, 0.f, 0.f);
        if (g < N_NODES) v = g_aggr4[(size_t)g * 32 + c4];
        uint2 hv, lv;
        hv.x = splitpair(v.x, v.y, lv.x);
        hv.y = splitpair(v.z, v.w, lv.y);
        *(uint2*)(smem + SM_ZH + row * KSTRB + c4 * 8) = hv;
        *(uint2*)(smem + SM_ZL + row * KSTRB + c4 * 8) = lv;
    }
    __syncthreads();

    const int aRow = wid * 16 + (lane & 7) + ((lane & 8) ? 8 : 0);
    const uint32_t aByte = (uint32_t)aRow * KSTRB + (((lane & 16) ? 8 : 0) * 2);
    const int bN = (lane & 7) + ((lane & 16) ? 8 : 0);
    const uint32_t bByte = (uint32_t)bN * KSTRB + (((lane & 8) ? 8 : 0) * 2);

    const int g4 = lane >> 2, t4 = lane & 3;
    const int rloc = wid * 16 + g4;

    float acc[16][4];
#pragma unroll
    for (int nt = 0; nt < 16; nt++)
#pragma unroll
        for (int i = 0; i < 4; i++) acc[nt][i] = 0.f;

    gemm128(sb, SM_ZH, SM_ZL, SM_W1H, SM_W1L, aByte, bByte, acc);

    {
        const float* b1s = (const float*)(smem + SM_B1);
#pragma unroll
        for (int nt = 0; nt < 16; nt++) {
            int col = nt * 8 + 2 * t4;
            float v0 = fmaxf(acc[nt][0] + b1s[col],     0.f);
            float v1 = fmaxf(acc[nt][1] + b1s[col + 1], 0.f);
            float v2 = fmaxf(acc[nt][2] + b1s[col],     0.f);
            float v3 = fmaxf(acc[nt][3] + b1s[col + 1], 0.f);
            uint32_t l0, l1;
            uint32_t h0 = splitpair(v0, v1, l0);
            uint32_t h1 = splitpair(v2, v3, l1);
            uint32_t o0 = rloc * KSTRB + col * 2;
            uint32_t o1 = (rloc + 8) * KSTRB + col * 2;
            *(uint32_t*)(smem + SM_ZH + o0) = h0;
            *(uint32_t*)(smem + SM_ZL + o0) = l0;
            *(uint32_t*)(smem + SM_ZH + o1) = h1;
            *(uint32_t*)(smem + SM_ZL + o1) = l1;
            acc[nt][0] = acc[nt][1] = acc[nt][2] = acc[nt][3] = 0.f;
        }
    }
    __syncwarp();

    gemm128(sb, SM_ZH, SM_ZL, SM_W2H, SM_W2L, aByte, bByte, acc);

    {
        const float* b2s = (const float*)(smem + SM_B2);
        int gr = base + rloc;
#pragma unroll
        for (int nt = 0; nt < 16; nt++) {
            int col = nt * 8 + 2 * t4;
            if (gr < N_NODES) {
                float2 v = make_float2(acc[nt][0] + b2s[col],
                                       acc[nt][1] + b2s[col + 1]);
                *(float2*)&out[(size_t)gr * HID + col] = v;
            }
            if (gr + 8 < N_NODES) {
                float2 v = make_float2(acc[nt][2] + b2s[col],
                                       acc[nt][3] + b2s[col + 1]);
                *(float2*)&out[(size_t)(gr + 8) * HID + col] = v;
            }
        }
    }
}

// ---------------------------------------------------------------------------
extern "C" void kernel_launch(void* const* d_in, const int* in_sizes, int n_in,
                              void* d_out, int out_size) {
    const float* x   = (const float*)d_in[0];
    const void*  ei  = d_in[1];
    const void*  ea  = d_in[2];
    const float* emb = (const float*)d_in[3];
    const float* We  = (const float*)d_in[4];
    const float* be  = (const float*)d_in[5];
    const float* W1  = (const float*)d_in[6];
    const float* b1  = (const float*)d_in[7];
    const float* W2  = (const float*)d_in[8];
    const float* b2  = (const float*)d_in[9];
    const float* eps = (const float*)d_in[10];
    float*       out = (float*)d_out;

    cudaFuncSetAttribute(mlp_mma_kernel,
                         cudaFuncAttributeMaxDynamicSharedMemorySize, SM_TOT);

    setup_kernel<<<NBLK + 8 + 136, 256>>>((const unsigned*)ei, emb, We, be, W1, W2);
    conv_kernel<<<(N_EDGES / 4 + 255) / 256, 256>>>(ei, ea);
    scan1_kernel<<<NBLK, 256>>>();
    scan2_kernel<<<1, 256>>>();
    scan3_kernel<<<NBLK, 256>>>();
    scatter_kernel<<<(N_EDGES / 2 + 255) / 256, 256>>>();
    aggr_kernel<<<(N_NODES * 32 + 255) / 256, 256>>>((const float4*)x, eps);
    mlp_mma_kernel<<<(N_NODES + 127) / 128, 256, SM_TOT>>>(b1, b2, out);
}

// round 10
// speedup vs baseline: 1.5347x; 1.0444x over previous
#include <cuda_runtime.h>
#include <cuda_bf16.h>
#include <cstdint>

#define N_NODES 50000
#define N_EDGES 640000
#define HID 128
#define KSTR 136                     // padded k-stride (bf16 elems)
#define KSTRB (KSTR * 2)             // 272 bytes
#define TILE_B (128 * KSTRB)         // 34816 bytes per bf16 tile
#define NBLK 196                     // ceil(N_NODES/256)

// ---------------- scratch (static __device__; no allocations) --------------
__device__ float4 g_aggr4[(size_t)N_NODES * (HID / 4)];
__device__ float4 g_proj4[16 * (HID / 4)];
__device__ int    g_idx64;
__device__ int    g_cnt[N_NODES];
__device__ int    g_off[N_NODES + 1];
__device__ int    g_cur[N_NODES];
__device__ int    g_bsum[256];
__device__ int    g_barA, g_barB, g_barC;
__device__ int      g_dst[N_EDGES];
__device__ unsigned g_srch[N_EDGES];     // (src << 4) | h
__device__ unsigned g_packed[N_EDGES];   // dst-sorted (src << 4) | h
// bf16 hi/lo weight tiles, transposed [n][k], stride KSTR
__device__ __align__(16) unsigned short g_w1h[128 * KSTR];
__device__ __align__(16) unsigned short g_w1l[128 * KSTR];
__device__ __align__(16) unsigned short g_w2h[128 * KSTR];
__device__ __align__(16) unsigned short g_w2l[128 * KSTR];

// ---------------- helpers ---------------------------------------------------
__device__ __forceinline__ uint32_t smem_u32(const void* p) {
    uint32_t a;
    asm("{ .reg .u64 t; cvta.to.shared.u64 t, %1; cvt.u32.u64 %0, t; }"
        : "=r"(a) : "l"(p));
    return a;
}
__device__ __forceinline__ void ldsm4(uint32_t* r, uint32_t a) {
    asm volatile("ldmatrix.sync.aligned.m8n8.x4.shared.b16 {%0,%1,%2,%3}, [%4];"
                 : "=r"(r[0]), "=r"(r[1]), "=r"(r[2]), "=r"(r[3]) : "r"(a));
}
__device__ __forceinline__ void mma_bf16(float* d, const uint32_t* a,
                                         uint32_t b0, uint32_t b1) {
    asm volatile(
        "mma.sync.aligned.m16n8k16.row.col.f32.bf16.bf16.f32 "
        "{%0,%1,%2,%3}, {%4,%5,%6,%7}, {%8,%9}, {%0,%1,%2,%3};"
        : "+f"(d[0]), "+f"(d[1]), "+f"(d[2]), "+f"(d[3])
        : "r"(a[0]), "r"(a[1]), "r"(a[2]), "r"(a[3]), "r"(b0), "r"(b1));
}
__device__ __forceinline__ uint32_t splitpair(float v0, float v1, uint32_t& lo) {
    __nv_bfloat16 h0 = __float2bfloat16(v0), h1 = __float2bfloat16(v1);
    __nv_bfloat16 l0 = __float2bfloat16(v0 - __bfloat162float(h0));
    __nv_bfloat16 l1 = __float2bfloat16(v1 - __bfloat162float(h1));
    lo = (uint32_t)__bfloat16_as_ushort(l0) |
         ((uint32_t)__bfloat16_as_ushort(l1) << 16);
    return (uint32_t)__bfloat16_as_ushort(h0) |
           ((uint32_t)__bfloat16_as_ushort(h1) << 16);
}
__device__ __forceinline__ void grid_barrier(int* bar) {
    __syncthreads();
    if (threadIdx.x == 0) {
        __threadfence();
        atomicAdd(bar, 1);
        while (atomicAdd(bar, 0) < NBLK) { }
        __threadfence();
    }
    __syncthreads();
}

// ---------------------------------------------------------------------------
// setup: blocks 0..195 zero counts (+ block0 probe + barrier reset),
//        blocks 196..203 proj table, blocks 204..339 weight split
// ---------------------------------------------------------------------------
__global__ void setup_kernel(const unsigned* __restrict__ ei_raw,
                             const float* __restrict__ emb,
                             const float* __restrict__ We,
                             const float* __restrict__ be,
                             const float* __restrict__ W1,
                             const float* __restrict__ W2) {
    int b = blockIdx.x;
    if (b < NBLK) {
        int i = b * 256 + threadIdx.x;
        if (i < N_NODES) g_cnt[i] = 0;
        if (b == 0 && threadIdx.x == 0) {
            unsigned acc = 0;
#pragma unroll
            for (int k = 0; k < 128; k++) acc |= ei_raw[2 * k + 1];
            g_idx64 = (acc == 0u) ? 1 : 0;
            g_barA = 0; g_barB = 0; g_barC = 0;
        }
    } else if (b < NBLK + 8) {
        int tid = (b - NBLK) * 256 + threadIdx.x;
        if (tid < 16 * HID) {
            int t = tid >> 7, j = tid & 127;
            float s = be[j];
#pragma unroll
            for (int d = 0; d < 8; d++)
                s = fmaf(emb[t * 8 + d], We[d * HID + j], s);
            ((float*)g_proj4)[tid] = s;
        }
    } else {
        int tid = (b - NBLK - 8) * 256 + threadIdx.x;
        if (tid < 2 * 128 * KSTR) {
            int mat = tid / (128 * KSTR);
            int rem = tid % (128 * KSTR);
            int n = rem / KSTR;
            int k = rem % KSTR;
            unsigned short hv = 0, lv = 0;
            if (k < 128) {
                const float* W = mat ? W2 : W1;
                float w = W[k * HID + n];
                __nv_bfloat16 h = __float2bfloat16(w);
                __nv_bfloat16 l = __float2bfloat16(w - __bfloat162float(h));
                hv = __bfloat16_as_ushort(h);
                lv = __bfloat16_as_ushort(l);
            }
            (mat ? g_w2h : g_w1h)[n * KSTR + k] = hv;
            (mat ? g_w2l : g_w1l)[n * KSTR + k] = lv;
        }
    }
}

// ---------------------------------------------------------------------------
// build: conv+hist -> scan -> scatter in ONE persistent kernel (196 blocks).
// ---------------------------------------------------------------------------
__global__ void __launch_bounds__(256)
build_kernel(const void* __restrict__ ei_v, const void* __restrict__ ea_v) {
    __shared__ int s[256];
    const int tid = threadIdx.x;
    const int b = blockIdx.x;
    const int gtid = b * 256 + tid;
    const int GSTRIDE = NBLK * 256;        // 50176

    // ---- phase 1: conv + histogram (grid-stride) ----
    if (g_idx64) {
        const long long* ei = (const long long*)ei_v;
        const long long* ea = (const long long*)ea_v;
#pragma unroll 4
        for (int e = gtid; e < N_EDGES; e += GSTRIDE) {
            int src = (int)ei[e], dst = (int)ei[N_EDGES + e];
            int h = (int)((ea[3LL * e] + 3 * ea[3LL * e + 1] + 7 * ea[3LL * e + 2]) & 15);
            g_srch[e] = ((unsigned)src << 4) | (unsigned)h;
            g_dst[e] = dst;
            atomicAdd(&g_cnt[dst], 1);
        }
    } else {
        const int* ei = (const int*)ei_v;
        const int* ea = (const int*)ea_v;
#pragma unroll 4
        for (int e = gtid; e < N_EDGES; e += GSTRIDE) {
            int src = ei[e], dst = ei[N_EDGES + e];
            int h = (ea[3 * e] + 3 * ea[3 * e + 1] + 7 * ea[3 * e + 2]) & 15;
            g_srch[e] = ((unsigned)src << 4) | (unsigned)h;
            g_dst[e] = dst;
            atomicAdd(&g_cnt[dst], 1);
        }
    }
    grid_barrier(&g_barA);

    // ---- phase 2a: local block scan of 256 counts, publish aggregate ----
    int node = b * 256 + tid;
    int c = (node < N_NODES) ? g_cnt[node] : 0;
    s[tid] = c;
    __syncthreads();
#pragma unroll
    for (int d = 1; d < 256; d <<= 1) {
        int t = (tid >= d) ? s[tid - d] : 0;
        __syncthreads();
        s[tid] += t;
        __syncthreads();
    }
    int local_excl = s[tid] - c;
    if (tid == 255) g_bsum[b] = s[255];
    grid_barrier(&g_barB);

    // ---- phase 2b: block prefix = sum of aggregates of blocks < b ----
    s[tid] = (tid < b) ? g_bsum[tid] : 0;
    __syncthreads();
#pragma unroll
    for (int d = 128; d > 0; d >>= 1) {
        if (tid < d) s[tid] += s[tid + d];
        __syncthreads();
    }
    int bpre = s[0];
    if (node < N_NODES) {
        int o = local_excl + bpre;
        g_off[node] = o;
        g_cur[node] = o;
    }
    if (b == 0 && tid == 0) g_off[N_NODES] = N_EDGES;
    grid_barrier(&g_barC);

    // ---- phase 3: scatter (grid-stride) ----
#pragma unroll 4
    for (int e = gtid; e < N_EDGES; e += GSTRIDE) {
        int pos = atomicAdd(&g_cur[g_dst[e]], 1);
        g_packed[pos] = g_srch[e];
    }
}

// ---------------------------------------------------------------------------
// aggregate: one warp per node, no atomics, 4-deep gather pipeline (R7 proven)
// ---------------------------------------------------------------------------
__global__ void __launch_bounds__(256)
aggr_kernel(const float4* __restrict__ x4, const float* __restrict__ epsp) {
    int node = (blockIdx.x * blockDim.x + threadIdx.x) >> 5;
    int lane = threadIdx.x & 31;
    if (node >= N_NODES) return;

    int beg = g_off[node], end = g_off[node + 1];
    float4 acc = make_float4(0.f, 0.f, 0.f, 0.f);

    for (int e = beg; e < end; e += 4) {
        int m = end - e;
        unsigned pk[4];
#pragma unroll
        for (int j = 0; j < 4; j++)
            pk[j] = (j < m) ? __ldg(&g_packed[e + j]) : 0u;
        float4 xv[4], pv[4];
#pragma unroll
        for (int j = 0; j < 4; j++) {
            if (j < m) {
                xv[j] = __ldg(&x4[(size_t)(pk[j] >> 4) * 32 + lane]);
                pv[j] = __ldg(&g_proj4[(pk[j] & 15u) * 32 + lane]);
            }
        }
#pragma unroll
        for (int j = 0; j < 4; j++) {
            if (j < m) {
                acc.x += fmaxf(xv[j].x + pv[j].x, 0.f);
                acc.y += fmaxf(xv[j].y + pv[j].y, 0.f);
                acc.z += fmaxf(xv[j].z + pv[j].z, 0.f);
                acc.w += fmaxf(xv[j].w + pv[j].w, 0.f);
            }
        }
    }
    float e1 = 1.0f + __ldg(epsp);
    float4 xn = __ldg(&x4[(size_t)node * 32 + lane]);
    acc.x = fmaf(e1, xn.x, acc.x);
    acc.y = fmaf(e1, xn.y, acc.y);
    acc.z = fmaf(e1, xn.z, acc.z);
    acc.w = fmaf(e1, xn.w, acc.w);
    g_aggr4[(size_t)node * 32 + lane] = acc;
}

// ---------------------------------------------------------------------------
// MLP via mma.sync bf16x3 — 2D warp tiling: warp (mw,nw) of 4x2 owns
// 32 rows x 64 cols. 1.5x less ldmatrix traffic than 16x128 ownership.
// ---------------------------------------------------------------------------
#define SM_B1  0
#define SM_B2  512
#define SM_ZH  1024
#define SM_ZL  (SM_ZH + TILE_B)
#define SM_W1H (SM_ZL + TILE_B)
#define SM_W1L (SM_W1H + TILE_B)
#define SM_W2H (SM_W1L + TILE_B)
#define SM_W2L (SM_W2H + TILE_B)
#define SM_TOT (SM_W2L + TILE_B)     // 209920 bytes

__device__ __forceinline__ void gemm2d(uint32_t sb, uint32_t zh, uint32_t zl,
                                       uint32_t wh, uint32_t wl,
                                       const uint32_t aB[2], const uint32_t bB[4],
                                       float acc[2][8][4]) {
#pragma unroll
    for (int ks = 0; ks < 8; ks++) {
        uint32_t k0b = ks * 32;
        uint32_t ah[2][4], al[2][4];
#pragma unroll
        for (int t = 0; t < 2; t++) {
            ldsm4(ah[t], sb + zh + aB[t] + k0b);
            ldsm4(al[t], sb + zl + aB[t] + k0b);
        }
#pragma unroll
        for (int u = 0; u < 4; u++) {
            uint32_t wH[4], wL[4];
            ldsm4(wH, sb + wh + bB[u] + k0b);
            ldsm4(wL, sb + wl + bB[u] + k0b);
#pragma unroll
            for (int t = 0; t < 2; t++) {
                mma_bf16(acc[t][2 * u],     ah[t], wH[0], wH[1]);
                mma_bf16(acc[t][2 * u],     ah[t], wL[0], wL[1]);
                mma_bf16(acc[t][2 * u],     al[t], wH[0], wH[1]);
                mma_bf16(acc[t][2 * u + 1], ah[t], wH[2], wH[3]);
                mma_bf16(acc[t][2 * u + 1], ah[t], wL[2], wL[3]);
                mma_bf16(acc[t][2 * u + 1], al[t], wH[2], wH[3]);
            }
        }
    }
}

__global__ void __launch_bounds__(256, 1)
mlp_mma_kernel(const float* __restrict__ b1, const float* __restrict__ b2,
               float* __restrict__ out) {
    extern __shared__ char smem[];
    const uint32_t sb = smem_u32(smem);
    const int tid = threadIdx.x, wid = tid >> 5, lane = tid & 31;
    const int base = blockIdx.x * 128;

    if (tid < 128) {
        ((float*)(smem + SM_B1))[tid] = b1[tid];
        ((float*)(smem + SM_B2))[tid] = b2[tid];
    }
    {
        const uint4* s[4] = {(const uint4*)g_w1h, (const uint4*)g_w1l,
                             (const uint4*)g_w2h, (const uint4*)g_w2l};
        uint4* d[4] = {(uint4*)(smem + SM_W1H), (uint4*)(smem + SM_W1L),
                       (uint4*)(smem + SM_W2H), (uint4*)(smem + SM_W2L)};
#pragma unroll
        for (int a = 0; a < 4; a++)
            for (int i = tid; i < TILE_B / 16; i += 256) d[a][i] = s[a][i];
    }

#pragma unroll
    for (int it = 0; it < 16; it++) {
        int idx = tid + it * 256;
        int row = idx >> 5, c4 = idx & 31;
        int g = base + row;
        float4 v = make_float4(0.f, 0.f, 0.f, 0.f);
        if (g < N_NODES) v = g_aggr4[(size_t)g * 32 + c4];
        uint2 hv, lv;
        hv.x = splitpair(v.x, v.y, lv.x);
        hv.y = splitpair(v.z, v.w, lv.y);
        *(uint2*)(smem + SM_ZH + row * KSTRB + c4 * 8) = hv;
        *(uint2*)(smem + SM_ZL + row * KSTRB + c4 * 8) = lv;
    }
    __syncthreads();

    const int mw = wid & 3;            // 4 M groups of 32 rows
    const int nw = wid >> 2;           // 2 N halves of 64 cols
    uint32_t aB[2], bB[4];
#pragma unroll
    for (int t = 0; t < 2; t++)
        aB[t] = (uint32_t)(32 * mw + 16 * t + (lane & 15)) * KSTRB +
                ((lane & 16) ? 16 : 0);
    const int nrow = (lane & 7) + ((lane & 16) ? 8 : 0);
#pragma unroll
    for (int u = 0; u < 4; u++)
        bB[u] = (uint32_t)(64 * nw + 16 * u + nrow) * KSTRB +
                ((lane & 8) ? 16 : 0);

    const int g4 = lane >> 2, t4 = lane & 3;

    float acc[2][8][4];
#pragma unroll
    for (int t = 0; t < 2; t++)
#pragma unroll
        for (int j = 0; j < 8; j++)
#pragma unroll
            for (int i = 0; i < 4; i++) acc[t][j][i] = 0.f;

    gemm2d(sb, SM_ZH, SM_ZL, SM_W1H, SM_W1L, aB, bB, acc);
    __syncthreads();   // all GEMM1 reads of z done before overwrite

    // epilogue1: h1 = relu(acc + b1) -> bf16 hi/lo back into z tiles
    {
        const float* b1s = (const float*)(smem + SM_B1);
#pragma unroll
        for (int t = 0; t < 2; t++) {
            int r0 = 32 * mw + 16 * t + g4;
#pragma unroll
            for (int j = 0; j < 8; j++) {
                int col = 64 * nw + 8 * j + 2 * t4;
                float v0 = fmaxf(acc[t][j][0] + b1s[col],     0.f);
                float v1 = fmaxf(acc[t][j][1] + b1s[col + 1], 0.f);
                float v2 = fmaxf(acc[t][j][2] + b1s[col],     0.f);
                float v3 = fmaxf(acc[t][j][3] + b1s[col + 1], 0.f);
                uint32_t l0, l1;
                uint32_t h0 = splitpair(v0, v1, l0);
                uint32_t h1 = splitpair(v2, v3, l1);
                uint32_t o0 = r0 * KSTRB + col * 2;
                uint32_t o1 = (r0 + 8) * KSTRB + col * 2;
                *(uint32_t*)(smem + SM_ZH + o0) = h0;
                *(uint32_t*)(smem + SM_ZL + o0) = l0;
                *(uint32_t*)(smem + SM_ZH + o1) = h1;
                *(uint32_t*)(smem + SM_ZL + o1) = l1;
                acc[t][j][0] = acc[t][j][1] = acc[t][j][2] = acc[t][j][3] = 0.f;
            }
        }
    }
    __syncthreads();

    gemm2d(sb, SM_ZH, SM_ZL, SM_W2H, SM_W2L, aB, bB, acc);

    // epilogue2: out = acc + b2
    {
        const float* b2s = (const float*)(smem + SM_B2);
#pragma unroll
        for (int t = 0; t < 2; t++) {
            int r0 = 32 * mw + 16 * t + g4;
            int gr0 = base + r0, gr1 = gr0 + 8;
#pragma unroll
            for (int j = 0; j < 8; j++) {
                int col = 64 * nw + 8 * j + 2 * t4;
                if (gr0 < N_NODES) {
                    float2 v = make_float2(acc[t][j][0] + b2s[col],
                                           acc[t][j][1] + b2s[col + 1]);
                    *(float2*)&out[(size_t)gr0 * HID + col] = v;
                }
                if (gr1 < N_NODES) {
                    float2 v = make_float2(acc[t][j][2] + b2s[col],
                                           acc[t][j][3] + b2s[col + 1]);
                    *(float2*)&out[(size_t)gr1 * HID + col] = v;
                }
            }
        }
    }
}

// ---------------------------------------------------------------------------
extern "C" void kernel_launch(void* const* d_in, const int* in_sizes, int n_in,
                              void* d_out, int out_size) {
    const float* x   = (const float*)d_in[0];
    const void*  ei  = d_in[1];
    const void*  ea  = d_in[2];
    const float* emb = (const float*)d_in[3];
    const float* We  = (const float*)d_in[4];
    const float* be  = (const float*)d_in[5];
    const float* W1  = (const float*)d_in[6];
    const float* b1  = (const float*)d_in[7];
    const float* W2  = (const float*)d_in[8];
    const float* b2  = (const float*)d_in[9];
    const float* eps = (const float*)d_in[10];
    float*       out = (float*)d_out;

    cudaFuncSetAttribute(mlp_mma_kernel,
                         cudaFuncAttributeMaxDynamicSharedMemorySize, SM_TOT);

    setup_kernel<<<NBLK + 8 + 136, 256>>>((const unsigned*)ei, emb, We, be, W1, W2);
    build_kernel<<<NBLK, 256>>>(ei, ea);
    aggr_kernel<<<(N_NODES * 32 + 255) / 256, 256>>>((const float4*)x, eps);
    mlp_mma_kernel<<<(N_NODES + 127) / 128, 256, SM_TOT>>>(b1, b2, out);
}

// round 11
// speedup vs baseline: 1.5766x; 1.0273x over previous
#include <cuda_runtime.h>
#include <cuda_bf16.h>
#include <cstdint>

#define N_NODES 50000
#define N_EDGES 640000
#define HID 128
#define KSTR 136                     // padded k-stride (bf16 elems)
#define KSTRB (KSTR * 2)             // 272 bytes
#define TILE_B (128 * KSTRB)         // 34816 bytes per 128-row bf16 tile
#define ZTILE_B (64 * KSTRB)         // 17408 bytes per 64-row z tile
#define NBLK 196                     // ceil(N_NODES/256)

// ---------------- scratch (static __device__; no allocations) --------------
__device__ float4 g_aggr4[(size_t)N_NODES * (HID / 4)];
__device__ float4 g_proj4[16 * (HID / 4)];
__device__ int    g_idx64;
__device__ int    g_cnt[N_NODES];
__device__ int    g_off[N_NODES + 1];
__device__ int    g_cur[N_NODES];
__device__ int    g_bsum[256];
__device__ int    g_barA, g_barB, g_barC;
__device__ int      g_dst[N_EDGES];
__device__ unsigned g_srch[N_EDGES];     // (src << 4) | h
__device__ unsigned g_packed[N_EDGES];   // dst-sorted (src << 4) | h
// bf16 hi/lo weight tiles, transposed [n][k], stride KSTR
__device__ __align__(16) unsigned short g_w1h[128 * KSTR];
__device__ __align__(16) unsigned short g_w1l[128 * KSTR];
__device__ __align__(16) unsigned short g_w2h[128 * KSTR];
__device__ __align__(16) unsigned short g_w2l[128 * KSTR];

// ---------------- helpers ---------------------------------------------------
__device__ __forceinline__ uint32_t smem_u32(const void* p) {
    uint32_t a;
    asm("{ .reg .u64 t; cvta.to.shared.u64 t, %1; cvt.u32.u64 %0, t; }"
        : "=r"(a) : "l"(p));
    return a;
}
__device__ __forceinline__ void ldsm4(uint32_t* r, uint32_t a) {
    asm volatile("ldmatrix.sync.aligned.m8n8.x4.shared.b16 {%0,%1,%2,%3}, [%4];"
                 : "=r"(r[0]), "=r"(r[1]), "=r"(r[2]), "=r"(r[3]) : "r"(a));
}
__device__ __forceinline__ void mma_bf16(float* d, const uint32_t* a,
                                         uint32_t b0, uint32_t b1) {
    asm volatile(
        "mma.sync.aligned.m16n8k16.row.col.f32.bf16.bf16.f32 "
        "{%0,%1,%2,%3}, {%4,%5,%6,%7}, {%8,%9}, {%0,%1,%2,%3};"
        : "+f"(d[0]), "+f"(d[1]), "+f"(d[2]), "+f"(d[3])
        : "r"(a[0]), "r"(a[1]), "r"(a[2]), "r"(a[3]), "r"(b0), "r"(b1));
}
__device__ __forceinline__ uint32_t splitpair(float v0, float v1, uint32_t& lo) {
    __nv_bfloat16 h0 = __float2bfloat16(v0), h1 = __float2bfloat16(v1);
    __nv_bfloat16 l0 = __float2bfloat16(v0 - __bfloat162float(h0));
    __nv_bfloat16 l1 = __float2bfloat16(v1 - __bfloat162float(h1));
    lo = (uint32_t)__bfloat16_as_ushort(l0) |
         ((uint32_t)__bfloat16_as_ushort(l1) << 16);
    return (uint32_t)__bfloat16_as_ushort(h0) |
           ((uint32_t)__bfloat16_as_ushort(h1) << 16);
}
__device__ __forceinline__ void grid_barrier(int* bar) {
    __syncthreads();
    if (threadIdx.x == 0) {
        __threadfence();
        atomicAdd(bar, 1);
        while (atomicAdd(bar, 0) < NBLK) { }
        __threadfence();
    }
    __syncthreads();
}

// ---------------------------------------------------------------------------
// setup: blocks 0..195 zero counts (+ block0 probe + barrier reset),
//        blocks 196..203 proj table, blocks 204..339 weight split
// ---------------------------------------------------------------------------
__global__ void setup_kernel(const unsigned* __restrict__ ei_raw,
                             const float* __restrict__ emb,
                             const float* __restrict__ We,
                             const float* __restrict__ be,
                             const float* __restrict__ W1,
                             const float* __restrict__ W2) {
    int b = blockIdx.x;
    if (b < NBLK) {
        int i = b * 256 + threadIdx.x;
        if (i < N_NODES) g_cnt[i] = 0;
        if (b == 0 && threadIdx.x == 0) {
            unsigned acc = 0;
#pragma unroll
            for (int k = 0; k < 128; k++) acc |= ei_raw[2 * k + 1];
            g_idx64 = (acc == 0u) ? 1 : 0;
            g_barA = 0; g_barB = 0; g_barC = 0;
        }
    } else if (b < NBLK + 8) {
        int tid = (b - NBLK) * 256 + threadIdx.x;
        if (tid < 16 * HID) {
            int t = tid >> 7, j = tid & 127;
            float s = be[j];
#pragma unroll
            for (int d = 0; d < 8; d++)
                s = fmaf(emb[t * 8 + d], We[d * HID + j], s);
            ((float*)g_proj4)[tid] = s;
        }
    } else {
        int tid = (b - NBLK - 8) * 256 + threadIdx.x;
        if (tid < 2 * 128 * KSTR) {
            int mat = tid / (128 * KSTR);
            int rem = tid % (128 * KSTR);
            int n = rem / KSTR;
            int k = rem % KSTR;
            unsigned short hv = 0, lv = 0;
            if (k < 128) {
                const float* W = mat ? W2 : W1;
                float w = W[k * HID + n];
                __nv_bfloat16 h = __float2bfloat16(w);
                __nv_bfloat16 l = __float2bfloat16(w - __bfloat162float(h));
                hv = __bfloat16_as_ushort(h);
                lv = __bfloat16_as_ushort(l);
            }
            (mat ? g_w2h : g_w1h)[n * KSTR + k] = hv;
            (mat ? g_w2l : g_w1l)[n * KSTR + k] = lv;
        }
    }
}

// ---------------------------------------------------------------------------
// build: conv+hist -> scan -> scatter in ONE persistent kernel (196 blocks).
// ---------------------------------------------------------------------------
__global__ void __launch_bounds__(256)
build_kernel(const void* __restrict__ ei_v, const void* __restrict__ ea_v) {
    __shared__ int s[256];
    const int tid = threadIdx.x;
    const int b = blockIdx.x;
    const int gtid = b * 256 + tid;
    const int GSTRIDE = NBLK * 256;        // 50176

    if (g_idx64) {
        const long long* ei = (const long long*)ei_v;
        const long long* ea = (const long long*)ea_v;
#pragma unroll 4
        for (int e = gtid; e < N_EDGES; e += GSTRIDE) {
            int src = (int)ei[e], dst = (int)ei[N_EDGES + e];
            int h = (int)((ea[3LL * e] + 3 * ea[3LL * e + 1] + 7 * ea[3LL * e + 2]) & 15);
            g_srch[e] = ((unsigned)src << 4) | (unsigned)h;
            g_dst[e] = dst;
            atomicAdd(&g_cnt[dst], 1);
        }
    } else {
        const int* ei = (const int*)ei_v;
        const int* ea = (const int*)ea_v;
#pragma unroll 4
        for (int e = gtid; e < N_EDGES; e += GSTRIDE) {
            int src = ei[e], dst = ei[N_EDGES + e];
            int h = (ea[3 * e] + 3 * ea[3 * e + 1] + 7 * ea[3 * e + 2]) & 15;
            g_srch[e] = ((unsigned)src << 4) | (unsigned)h;
            g_dst[e] = dst;
            atomicAdd(&g_cnt[dst], 1);
        }
    }
    grid_barrier(&g_barA);

    int node = b * 256 + tid;
    int c = (node < N_NODES) ? g_cnt[node] : 0;
    s[tid] = c;
    __syncthreads();
#pragma unroll
    for (int d = 1; d < 256; d <<= 1) {
        int t = (tid >= d) ? s[tid - d] : 0;
        __syncthreads();
        s[tid] += t;
        __syncthreads();
    }
    int local_excl = s[tid] - c;
    if (tid == 255) g_bsum[b] = s[255];
    grid_barrier(&g_barB);

    s[tid] = (tid < b) ? g_bsum[tid] : 0;
    __syncthreads();
#pragma unroll
    for (int d = 128; d > 0; d >>= 1) {
        if (tid < d) s[tid] += s[tid + d];
        __syncthreads();
    }
    int bpre = s[0];
    if (node < N_NODES) {
        int o = local_excl + bpre;
        g_off[node] = o;
        g_cur[node] = o;
    }
    if (b == 0 && tid == 0) g_off[N_NODES] = N_EDGES;
    grid_barrier(&g_barC);

#pragma unroll 4
    for (int e = gtid; e < N_EDGES; e += GSTRIDE) {
        int pos = atomicAdd(&g_cur[g_dst[e]], 1);
        g_packed[pos] = g_srch[e];
    }
}

// ---------------------------------------------------------------------------
// aggregate: one warp per node, no atomics, 4-deep gather pipeline (proven)
// ---------------------------------------------------------------------------
__global__ void __launch_bounds__(256)
aggr_kernel(const float4* __restrict__ x4, const float* __restrict__ epsp) {
    int node = (blockIdx.x * blockDim.x + threadIdx.x) >> 5;
    int lane = threadIdx.x & 31;
    if (node >= N_NODES) return;

    int beg = g_off[node], end = g_off[node + 1];
    float4 acc = make_float4(0.f, 0.f, 0.f, 0.f);

    for (int e = beg; e < end; e += 4) {
        int m = end - e;
        unsigned pk[4];
#pragma unroll
        for (int j = 0; j < 4; j++)
            pk[j] = (j < m) ? __ldg(&g_packed[e + j]) : 0u;
        float4 xv[4], pv[4];
#pragma unroll
        for (int j = 0; j < 4; j++) {
            if (j < m) {
                xv[j] = __ldg(&x4[(size_t)(pk[j] >> 4) * 32 + lane]);
                pv[j] = __ldg(&g_proj4[(pk[j] & 15u) * 32 + lane]);
            }
        }
#pragma unroll
        for (int j = 0; j < 4; j++) {
            if (j < m) {
                acc.x += fmaxf(xv[j].x + pv[j].x, 0.f);
                acc.y += fmaxf(xv[j].y + pv[j].y, 0.f);
                acc.z += fmaxf(xv[j].z + pv[j].z, 0.f);
                acc.w += fmaxf(xv[j].w + pv[j].w, 0.f);
            }
        }
    }
    float e1 = 1.0f + __ldg(epsp);
    float4 xn = __ldg(&x4[(size_t)node * 32 + lane]);
    acc.x = fmaf(e1, xn.x, acc.x);
    acc.y = fmaf(e1, xn.y, acc.y);
    acc.z = fmaf(e1, xn.z, acc.z);
    acc.w = fmaf(e1, xn.w, acc.w);
    g_aggr4[(size_t)node * 32 + lane] = acc;
}

// ---------------------------------------------------------------------------
// MLP via mma.sync bf16x3 — 64 rows/CTA, weights streamed (W1 then W2),
// ~103KB smem -> 2 CTAs/SM = 16 warps/SM for latency hiding.
// Warp grid 2Mx4N: warp owns 32 rows x 32 cols.
// ---------------------------------------------------------------------------
#define SM_B1  0
#define SM_B2  512
#define SM_ZH  1024
#define SM_ZL  (SM_ZH + ZTILE_B)
#define SM_WH  (SM_ZL + ZTILE_B)
#define SM_WL  (SM_WH + TILE_B)
#define SM_TOT (SM_WL + TILE_B)      // 105472 bytes

__device__ __forceinline__ void gemm64(uint32_t sb,
                                       const uint32_t aB[2], const uint32_t bB[2],
                                       float acc[2][4][4]) {
#pragma unroll
    for (int ks = 0; ks < 8; ks++) {
        uint32_t k0b = ks * 32;
        uint32_t ah[2][4], al[2][4];
#pragma unroll
        for (int t = 0; t < 2; t++) {
            ldsm4(ah[t], sb + SM_ZH + aB[t] + k0b);
            ldsm4(al[t], sb + SM_ZL + aB[t] + k0b);
        }
#pragma unroll
        for (int u = 0; u < 2; u++) {
            uint32_t wH[4], wL[4];
            ldsm4(wH, sb + SM_WH + bB[u] + k0b);
            ldsm4(wL, sb + SM_WL + bB[u] + k0b);
#pragma unroll
            for (int t = 0; t < 2; t++) {
                mma_bf16(acc[t][2 * u],     ah[t], wH[0], wH[1]);
                mma_bf16(acc[t][2 * u],     ah[t], wL[0], wL[1]);
                mma_bf16(acc[t][2 * u],     al[t], wH[0], wH[1]);
                mma_bf16(acc[t][2 * u + 1], ah[t], wH[2], wH[3]);
                mma_bf16(acc[t][2 * u + 1], ah[t], wL[2], wL[3]);
                mma_bf16(acc[t][2 * u + 1], al[t], wH[2], wH[3]);
            }
        }
    }
}

__device__ __forceinline__ void copy_w(char* smem, int tid,
                                       const uint4* wh, const uint4* wl) {
    uint4* dh = (uint4*)(smem + SM_WH);
    uint4* dl = (uint4*)(smem + SM_WL);
#pragma unroll
    for (int i = tid; i < TILE_B / 16; i += 256) {
        dh[i] = wh[i];
        dl[i] = wl[i];
    }
}

__global__ void __launch_bounds__(256, 2)
mlp_mma_kernel(const float* __restrict__ b1, const float* __restrict__ b2,
               float* __restrict__ out) {
    extern __shared__ char smem[];
    const uint32_t sb = smem_u32(smem);
    const int tid = threadIdx.x, wid = tid >> 5, lane = tid & 31;
    const int base = blockIdx.x * 64;

    if (tid < 128) {
        ((float*)(smem + SM_B1))[tid] = b1[tid];
        ((float*)(smem + SM_B2))[tid] = b2[tid];
    }
    copy_w(smem, tid, (const uint4*)g_w1h, (const uint4*)g_w1l);

    // z tile from aggr -> bf16 hi/lo (64 rows x 32 float4 = 2048)
#pragma unroll
    for (int it = 0; it < 8; it++) {
        int idx = tid + it * 256;
        int row = idx >> 5, c4 = idx & 31;
        int g = base + row;
        float4 v = make_float4(0.f, 0.f, 0.f, 0.f);
        if (g < N_NODES) v = g_aggr4[(size_t)g * 32 + c4];
        uint2 hv, lv;
        hv.x = splitpair(v.x, v.y, lv.x);
        hv.y = splitpair(v.z, v.w, lv.y);
        *(uint2*)(smem + SM_ZH + row * KSTRB + c4 * 8) = hv;
        *(uint2*)(smem + SM_ZL + row * KSTRB + c4 * 8) = lv;
    }
    __syncthreads();

    const int mw = wid & 1;            // 2 M groups of 32 rows
    const int nw = wid >> 1;           // 4 N groups of 32 cols
    uint32_t aB[2], bB[2];
#pragma unroll
    for (int t = 0; t < 2; t++)
        aB[t] = (uint32_t)(32 * mw + 16 * t + (lane & 15)) * KSTRB +
                ((lane & 16) ? 16 : 0);
    const int nrow = (lane & 7) + ((lane & 16) ? 8 : 0);
#pragma unroll
    for (int u = 0; u < 2; u++)
        bB[u] = (uint32_t)(32 * nw + 16 * u + nrow) * KSTRB +
                ((lane & 8) ? 16 : 0);

    const int g4 = lane >> 2, t4 = lane & 3;

    float acc[2][4][4];
#pragma unroll
    for (int t = 0; t < 2; t++)
#pragma unroll
        for (int j = 0; j < 4; j++)
#pragma unroll
            for (int i = 0; i < 4; i++) acc[t][j][i] = 0.f;

    gemm64(sb, aB, bB, acc);
    __syncthreads();   // all GEMM1 reads of z/W1 done

    // epilogue1: h1 = relu(acc + b1) -> z tiles; also stream in W2
    {
        const float* b1s = (const float*)(smem + SM_B1);
#pragma unroll
        for (int t = 0; t < 2; t++) {
            int r0 = 32 * mw + 16 * t + g4;
#pragma unroll
            for (int j = 0; j < 4; j++) {
                int col = 32 * nw + 8 * j + 2 * t4;
                float v0 = fmaxf(acc[t][j][0] + b1s[col],     0.f);
                float v1 = fmaxf(acc[t][j][1] + b1s[col + 1], 0.f);
                float v2 = fmaxf(acc[t][j][2] + b1s[col],     0.f);
                float v3 = fmaxf(acc[t][j][3] + b1s[col + 1], 0.f);
                uint32_t l0, l1;
                uint32_t h0 = splitpair(v0, v1, l0);
                uint32_t h1 = splitpair(v2, v3, l1);
                uint32_t o0 = r0 * KSTRB + col * 2;
                uint32_t o1 = (r0 + 8) * KSTRB + col * 2;
                *(uint32_t*)(smem + SM_ZH + o0) = h0;
                *(uint32_t*)(smem + SM_ZL + o0) = l0;
                *(uint32_t*)(smem + SM_ZH + o1) = h1;
                *(uint32_t*)(smem + SM_ZL + o1) = l1;
                acc[t][j][0] = acc[t][j][1] = acc[t][j][2] = acc[t][j][3] = 0.f;
            }
        }
    }
    copy_w(smem, tid, (const uint4*)g_w2h, (const uint4*)g_w2l);
    __syncthreads();

    gemm64(sb, aB, bB, acc);

    // epilogue2: out = acc + b2
    {
        const float* b2s = (const float*)(smem + SM_B2);
#pragma unroll
        for (int t = 0; t < 2; t++) {
            int r0 = 32 * mw + 16 * t + g4;
            int gr0 = base + r0, gr1 = gr0 + 8;
#pragma unroll
            for (int j = 0; j < 4; j++) {
                int col = 32 * nw + 8 * j + 2 * t4;
                if (gr0 < N_NODES) {
                    float2 v = make_float2(acc[t][j][0] + b2s[col],
                                           acc[t][j][1] + b2s[col + 1]);
                    *(float2*)&out[(size_t)gr0 * HID + col] = v;
                }
                if (gr1 < N_NODES) {
                    float2 v = make_float2(acc[t][j][2] + b2s[col],
                                           acc[t][j][3] + b2s[col + 1]);
                    *(float2*)&out[(size_t)gr1 * HID + col] = v;
                }
            }
        }
    }
}

// ---------------------------------------------------------------------------
extern "C" void kernel_launch(void* const* d_in, const int* in_sizes, int n_in,
                              void* d_out, int out_size) {
    const float* x   = (const float*)d_in[0];
    const void*  ei  = d_in[1];
    const void*  ea  = d_in[2];
    const float* emb = (const float*)d_in[3];
    const float* We  = (const float*)d_in[4];
    const float* be  = (const float*)d_in[5];
    const float* W1  = (const float*)d_in[6];
    const float* b1  = (const float*)d_in[7];
    const float* W2  = (const float*)d_in[8];
    const float* b2  = (const float*)d_in[9];
    const float* eps = (const float*)d_in[10];
    float*       out = (float*)d_out;

    cudaFuncSetAttribute(mlp_mma_kernel,
                         cudaFuncAttributeMaxDynamicSharedMemorySize, SM_TOT);

    setup_kernel<<<NBLK + 8 + 136, 256>>>((const unsigned*)ei, emb, We, be, W1, W2);
    build_kernel<<<NBLK, 256>>>(ei, ea);
    aggr_kernel<<<(N_NODES * 32 + 255) / 256, 256>>>((const float4*)x, eps);
    mlp_mma_kernel<<<(N_NODES + 63) / 64, 256, SM_TOT>>>(b1, b2, out);
}